// round 1
// baseline (speedup 1.0000x reference)
#include <cuda_runtime.h>
#include <cuda_bf16.h>
#include <cstdint>

// ---------------------------------------------------------------------------
// Problem constants
// ---------------------------------------------------------------------------
#define BB      2
#define LL      2048
#define ROWS    (BB*LL)        // 4096 tokens
#define DM      256            // d_model
#define DI      512            // d_inner
#define DS      16             // d_state
#define DR      16             // dt_rank
#define NL      16             // layers
#define NC      32             // scan chunks per sequence
#define CT      (LL/NC)        // 64 steps per chunk

// ---------------------------------------------------------------------------
// Scratch (static device allocations — no cudaMalloc allowed)
// ---------------------------------------------------------------------------
__device__ float g_h  [ROWS*DM];     // block output / embedding
__device__ float g_res[ROWS*DM];     // residual stream
__device__ float g_hn [ROWS*DM];     // normed input
__device__ float g_xz [ROWS*2*DI];   // in_proj output (x | z)
__device__ float g_xc [ROWS*DI];     // conv+silu output
__device__ float g_dbc[ROWS*48];     // x_proj output (dt_in | B | C)
__device__ float g_dt [ROWS*DI];     // softplus(dt_proj)
__device__ float g_y  [ROWS*DI];     // scan output * silu(z)
__device__ float g_ap [BB*DI*DS*NC]; // chunk prod(dA)
__device__ float g_hl [BB*DI*DS*NC]; // chunk local h final
__device__ float g_hi [BB*DI*DS*NC]; // chunk initial h

__device__ __forceinline__ float softplusf(float v) {
    return v > 20.f ? v : log1pf(__expf(v));
}
__device__ __forceinline__ float siluf(float v) {
    return v / (1.f + __expf(-v));
}

// ---------------------------------------------------------------------------
// Embedding gather
// ---------------------------------------------------------------------------
__global__ void embed_k(const int* __restrict__ ids,
                        const float* __restrict__ emb) {
    int row = blockIdx.x, t = threadIdx.x;
    g_h[(size_t)row*DM + t] = emb[(size_t)ids[row]*DM + t];
}

// ---------------------------------------------------------------------------
// residual += h (or res = h when first); hn = rmsnorm(res) * w
// One block per token row, 256 threads (= DM).
// ---------------------------------------------------------------------------
__global__ void norm_k(const float* __restrict__ w, int first) {
    int row = blockIdx.x, t = threadIdx.x;
    size_t i = (size_t)row*DM + t;
    float v = g_h[i];
    if (!first) v += g_res[i];
    g_res[i] = v;
    float ss = v*v;
    #pragma unroll
    for (int o = 16; o > 0; o >>= 1) ss += __shfl_xor_sync(0xffffffffu, ss, o);
    __shared__ float red[8];
    __shared__ float s_scale;
    if ((t & 31) == 0) red[t >> 5] = ss;
    __syncthreads();
    if (t == 0) {
        float tot = 0.f;
        #pragma unroll
        for (int k = 0; k < 8; k++) tot += red[k];
        s_scale = rsqrtf(tot * (1.f/DM) + 1e-5f);
    }
    __syncthreads();
    g_hn[i] = v * s_scale * w[t];
}

// ---------------------------------------------------------------------------
// SGEMM: C[M,N] = A[M,K] * W[N,K]^T   (W row-major (N,K), as all weights are)
// 128x128 tile, BK=8, 256 threads, 8x8 per thread.
// MODE 0: plain store.  MODE 1: softplus(acc + bias[n]).
// ---------------------------------------------------------------------------
template<int MODE>
__global__ __launch_bounds__(256)
void gemm_k(const float* __restrict__ A, int lda,
            const float* __restrict__ W,
            float* __restrict__ C, int ldc,
            int N, int K, const float* __restrict__ bias) {
    __shared__ float As[8][128];
    __shared__ float Ws[8][128];
    const int tid  = threadIdx.x;
    const int m0   = blockIdx.y * 128;
    const int n0   = blockIdx.x * 128;
    const int irow = tid >> 1;
    const int icol = (tid & 1) * 4;
    const int trow = tid >> 4;     // 0..15
    const int tcol = tid & 15;     // 0..15

    float acc[8][8];
    #pragma unroll
    for (int i = 0; i < 8; i++)
        #pragma unroll
        for (int j = 0; j < 8; j++) acc[i][j] = 0.f;

    for (int k0 = 0; k0 < K; k0 += 8) {
        float4 av = *reinterpret_cast<const float4*>(
            A + (size_t)(m0 + irow)*lda + k0 + icol);
        As[icol+0][irow] = av.x; As[icol+1][irow] = av.y;
        As[icol+2][irow] = av.z; As[icol+3][irow] = av.w;

        float4 wv = make_float4(0.f,0.f,0.f,0.f);
        if (n0 + irow < N)
            wv = *reinterpret_cast<const float4*>(
                W + (size_t)(n0 + irow)*K + k0 + icol);
        Ws[icol+0][irow] = wv.x; Ws[icol+1][irow] = wv.y;
        Ws[icol+2][irow] = wv.z; Ws[icol+3][irow] = wv.w;
        __syncthreads();

        #pragma unroll
        for (int kk = 0; kk < 8; kk++) {
            float a[8], b[8];
            #pragma unroll
            for (int i = 0; i < 8; i++) a[i] = As[kk][trow*8 + i];
            #pragma unroll
            for (int j = 0; j < 8; j++) b[j] = Ws[kk][tcol*8 + j];
            #pragma unroll
            for (int i = 0; i < 8; i++)
                #pragma unroll
                for (int j = 0; j < 8; j++) acc[i][j] += a[i]*b[j];
        }
        __syncthreads();
    }

    #pragma unroll
    for (int i = 0; i < 8; i++) {
        int m = m0 + trow*8 + i;
        #pragma unroll
        for (int j = 0; j < 8; j++) {
            int n = n0 + tcol*8 + j;
            if (n < N) {
                float v = acc[i][j];
                if (MODE == 1) v = softplusf(v + bias[n]);
                C[(size_t)m*ldc + n] = v;
            }
        }
    }
}

// ---------------------------------------------------------------------------
// Depthwise causal conv (width 4) + bias + silu.  x = xz[:, :DI]
// ---------------------------------------------------------------------------
__global__ void conv_k(const float* __restrict__ cw,
                       const float* __restrict__ cb) {
    int g = blockIdx.x*256 + threadIdx.x;       // 0..ROWS*DI
    int d = g & (DI-1);
    int row = g >> 9;
    int b = row >> 11;
    int l = row & (LL-1);
    float acc = cb[d];
    #pragma unroll
    for (int j = 0; j < 4; j++) {
        int ls = l - 3 + j;
        if (ls >= 0)
            acc += cw[d*4 + j] * g_xz[(size_t)((b<<11) + ls)*(2*DI) + d];
    }
    g_xc[(size_t)row*DI + d] = siluf(acc);
}

// ---------------------------------------------------------------------------
// Selective scan, chunked 2-pass.
// Thread = (b, d); states in registers; E-power trick avoids 16x MUFU.
// dA_s = exp(dt*A_s); with A_s = (s+1)*A_0 (S4D-real) -> dA_s = E^(s+1).
// ---------------------------------------------------------------------------
__device__ __forceinline__ void compute_dA(float dA[DS], const float A[DS],
                                           float dtv, bool fast) {
    if (fast) {
        float E  = __expf(A[0]*dtv);
        float e2 = E*E, e4 = e2*e2, e8 = e4*e4;
        dA[0]=E;        dA[1]=e2;        dA[2]=e2*E;        dA[3]=e4;
        dA[4]=e4*E;     dA[5]=e4*e2;     dA[6]=e4*e2*E;     dA[7]=e8;
        dA[8]=e8*E;     dA[9]=e8*e2;     dA[10]=e8*e2*E;    dA[11]=e8*e4;
        dA[12]=e8*e4*E; dA[13]=e8*e4*e2; dA[14]=e8*e4*e2*E; dA[15]=e8*e8;
    } else {
        #pragma unroll
        for (int s = 0; s < DS; s++) dA[s] = __expf(A[s]*dtv);
    }
}

__device__ __forceinline__ void load_A(const float* __restrict__ A_log,
                                       int d, float A[DS], bool& fast) {
    #pragma unroll
    for (int s = 0; s < DS; s++) A[s] = -__expf(A_log[d*DS + s]);
    fast = true;
    #pragma unroll
    for (int s = 1; s < DS; s++)
        fast = fast && (fabsf(A[s] - (float)(s+1)*A[0]) <= 1e-3f*fabsf(A[s]));
}

// grid: BB*NC*2 blocks of 256; block covers 256 d-channels of one (b, chunk)
__global__ __launch_bounds__(256)
void scan1_k(const float* __restrict__ A_log) {
    int bi = blockIdx.x;
    int b     = bi >> 6;
    int chunk = (bi >> 1) & (NC-1);
    int d     = ((bi & 1) << 8) + threadIdx.x;

    float A[DS]; bool fast;
    load_A(A_log, d, A, fast);

    float h[DS], ap[DS];
    #pragma unroll
    for (int s = 0; s < DS; s++) { h[s] = 0.f; ap[s] = 1.f; }

    int base = b*LL + chunk*CT;
    for (int t = 0; t < CT; t++) {
        size_t row = base + t;
        float dtv = __ldg(g_dt + row*DI + d);
        float xv  = __ldg(g_xc + row*DI + d);
        float c   = dtv * xv;
        float dA[DS];
        compute_dA(dA, A, dtv, fast);
        const float* Bp = g_dbc + row*48 + 16;
        #pragma unroll
        for (int s = 0; s < DS; s++) {
            float Bv = __ldg(Bp + s);
            h[s]  = dA[s]*h[s] + c*Bv;
            ap[s] *= dA[s];
        }
    }
    size_t idx0 = ((size_t)(b*DI + d)*DS)*NC + chunk;
    #pragma unroll
    for (int s = 0; s < DS; s++) {
        g_ap[idx0 + (size_t)s*NC] = ap[s];
        g_hl[idx0 + (size_t)s*NC] = h[s];
    }
}

// serial scan across NC chunk carries: one thread per (b,d,s)
__global__ void combine_k() {
    int i = blockIdx.x*256 + threadIdx.x;     // 0..BB*DI*DS
    size_t base = (size_t)i * NC;
    float h = 0.f;
    #pragma unroll
    for (int c = 0; c < NC; c++) {
        g_hi[base + c] = h;
        h = g_ap[base + c]*h + g_hl[base + c];
    }
}

__global__ __launch_bounds__(256)
void scan2_k(const float* __restrict__ A_log,
             const float* __restrict__ Dp) {
    int bi = blockIdx.x;
    int b     = bi >> 6;
    int chunk = (bi >> 1) & (NC-1);
    int d     = ((bi & 1) << 8) + threadIdx.x;

    float A[DS]; bool fast;
    load_A(A_log, d, A, fast);
    float Dd = Dp[d];

    size_t idx0 = ((size_t)(b*DI + d)*DS)*NC + chunk;
    float h[DS];
    #pragma unroll
    for (int s = 0; s < DS; s++) h[s] = g_hi[idx0 + (size_t)s*NC];

    int base = b*LL + chunk*CT;
    for (int t = 0; t < CT; t++) {
        size_t row = base + t;
        float dtv = __ldg(g_dt + row*DI + d);
        float xv  = __ldg(g_xc + row*DI + d);
        float c   = dtv * xv;
        float dA[DS];
        compute_dA(dA, A, dtv, fast);
        const float* Bp = g_dbc + row*48 + 16;
        float acc = 0.f;
        #pragma unroll
        for (int s = 0; s < DS; s++) {
            float Bv = __ldg(Bp + s);
            float Cv = __ldg(Bp + 16 + s);
            h[s] = dA[s]*h[s] + c*Bv;
            acc += h[s]*Cv;
        }
        float zv = __ldg(g_xz + row*(2*DI) + DI + d);
        g_y[row*DI + d] = (acc + Dd*xv) * siluf(zv);
    }
}

// ---------------------------------------------------------------------------
// Host side
// ---------------------------------------------------------------------------
extern "C" void kernel_launch(void* const* d_in, const int* in_sizes, int n_in,
                              void* d_out, int out_size) {
    const int*   ids  = (const int*)  d_in[0];
    const float* emb  = (const float*)d_in[1];
    const float* inw  = (const float*)d_in[2];   // (NL, 2*DI, DM)
    const float* cw   = (const float*)d_in[3];   // (NL, DI, 4)
    const float* cb   = (const float*)d_in[4];   // (NL, DI)
    const float* xw   = (const float*)d_in[5];   // (NL, 48, DI)
    const float* dtw  = (const float*)d_in[6];   // (NL, DI, DR)
    const float* dtb  = (const float*)d_in[7];   // (NL, DI)
    const float* alog = (const float*)d_in[8];   // (NL, DI, DS)
    const float* Dp   = (const float*)d_in[9];   // (NL, DI)
    const float* ow   = (const float*)d_in[10];  // (NL, DM, DI)
    const float* nw   = (const float*)d_in[11];  // (NL, DM)
    const float* nfw  = (const float*)d_in[12];  // (DM)
    const float* lmw  = (const float*)d_in[13];  // (20, DM)
    float* out = (float*)d_out;

    float *p_hn, *p_xz, *p_xc, *p_dbc, *p_dt, *p_y, *p_h;
    cudaGetSymbolAddress((void**)&p_hn,  g_hn);
    cudaGetSymbolAddress((void**)&p_xz,  g_xz);
    cudaGetSymbolAddress((void**)&p_xc,  g_xc);
    cudaGetSymbolAddress((void**)&p_dbc, g_dbc);
    cudaGetSymbolAddress((void**)&p_dt,  g_dt);
    cudaGetSymbolAddress((void**)&p_y,   g_y);
    cudaGetSymbolAddress((void**)&p_h,   g_h);

    embed_k<<<ROWS, DM>>>(ids, emb);

    for (int l = 0; l < NL; l++) {
        norm_k<<<ROWS, DM>>>(nw + (size_t)l*DM, l == 0);

        // in_proj: (4096,256) x (1024,256)^T -> xz (4096,1024)
        gemm_k<0><<<dim3(8, 32), 256>>>(p_hn, DM, inw + (size_t)l*2*DI*DM,
                                        p_xz, 2*DI, 2*DI, DM, nullptr);
        // depthwise conv + silu
        conv_k<<<ROWS*DI/256, 256>>>(cw + (size_t)l*DI*4, cb + (size_t)l*DI);

        // x_proj: (4096,512) x (48,512)^T -> dbc (4096,48)
        gemm_k<0><<<dim3(1, 32), 256>>>(p_xc, DI, xw + (size_t)l*48*DI,
                                        p_dbc, 48, 48, DI, nullptr);
        // dt_proj + bias + softplus: (4096,16) x (512,16)^T -> dt (4096,512)
        gemm_k<1><<<dim3(4, 32), 256>>>(p_dbc, 48, dtw + (size_t)l*DI*DR,
                                        p_dt, DI, DI, DR, dtb + (size_t)l*DI);
        // chunked selective scan
        scan1_k<<<BB*NC*2, 256>>>(alog + (size_t)l*DI*DS);
        combine_k<<<BB*DI*DS/256, 256>>>();
        scan2_k<<<BB*NC*2, 256>>>(alog + (size_t)l*DI*DS, Dp + (size_t)l*DI);

        // out_proj: (4096,512) x (256,512)^T -> h (4096,256)
        gemm_k<0><<<dim3(2, 32), 256>>>(p_y, DI, ow + (size_t)l*DM*DI,
                                        p_h, DM, DM, DI, nullptr);
    }

    // final residual + norm + lm_head
    norm_k<<<ROWS, DM>>>(nfw, 0);
    gemm_k<0><<<dim3(1, 32), 256>>>(p_hn, DM, lmw, out, 20, 20, DM, nullptr);
}

// round 5
// speedup vs baseline: 1.9503x; 1.9503x over previous
#include <cuda_runtime.h>
#include <cuda_bf16.h>
#include <cstdint>

// ---------------------------------------------------------------------------
// Problem constants
// ---------------------------------------------------------------------------
#define BB      2
#define LL      2048
#define ROWS    (BB*LL)        // 4096 tokens
#define DM      256            // d_model
#define DI      512            // d_inner
#define DS      16             // d_state
#define DR      16             // dt_rank
#define NL      16             // layers
#define NC      32             // scan chunks per sequence
#define CT      (LL/NC)        // 64 steps per chunk
#define NDT     544            // fused dt|B|C GEMM width (512 + 32)

// ---------------------------------------------------------------------------
// Scratch (static device allocations — no cudaMalloc allowed)
// ---------------------------------------------------------------------------
__device__ float g_h  [ROWS*DM];     // block output / embedding
__device__ float g_res[ROWS*DM];     // residual stream
__device__ float g_hn [ROWS*DM];     // normed input
__device__ float g_xz [ROWS*2*DI];   // in_proj output (x | z)
__device__ float g_xc [ROWS*DI];     // conv+silu output
__device__ float g_dbc[ROWS*32];     // B | C per token
__device__ float g_dt [ROWS*DI];     // softplus(dt)
__device__ float g_y  [ROWS*DI];     // scan output * silu(z)
__device__ float g_ap [BB*DI*DS*NC]; // chunk prod(dA)
__device__ float g_hl [BB*DI*DS*NC]; // chunk local h final
__device__ float g_hi [BB*DI*DS*NC]; // chunk initial h
__device__ float g_wall[NL*NDT*DI];  // fused (W_dt | xw_B | xw_C) weights

__device__ __forceinline__ float softplusf(float v) {
    return v > 20.f ? v : log1pf(__expf(v));
}
__device__ __forceinline__ float siluf(float v) {
    return v / (1.f + __expf(-v));
}
__device__ __forceinline__ uint32_t f2tf(float f) {
    uint32_t u; asm("cvt.rna.tf32.f32 %0, %1;" : "=r"(u) : "f"(f)); return u;
}
__device__ __forceinline__ void mma8(float* c, const uint32_t* a, const uint32_t* b) {
    asm volatile(
        "mma.sync.aligned.m16n8k8.row.col.f32.tf32.tf32.f32 "
        "{%0,%1,%2,%3}, {%4,%5,%6,%7}, {%8,%9}, {%0,%1,%2,%3};"
        : "+f"(c[0]), "+f"(c[1]), "+f"(c[2]), "+f"(c[3])
        : "r"(a[0]), "r"(a[1]), "r"(a[2]), "r"(a[3]), "r"(b[0]), "r"(b[1]));
}

// ---------------------------------------------------------------------------
// Embedding gather
// ---------------------------------------------------------------------------
__global__ void embed_k(const int* __restrict__ ids,
                        const float* __restrict__ emb) {
    int row = blockIdx.x, t = threadIdx.x;
    g_h[(size_t)row*DM + t] = emb[(size_t)ids[row]*DM + t];
}

// ---------------------------------------------------------------------------
// Fused weight precompute:
//   rows 0..511 : W_dt[n][k] = sum_r dtw[n][r] * xw[r][k]
//   rows 512..543: xw[16+(n-512)][k]   (B and C projections)
// ---------------------------------------------------------------------------
__global__ void wdt_k(const float* __restrict__ xw,
                      const float* __restrict__ dtw) {
    size_t i = (size_t)blockIdx.x*256 + threadIdx.x;   // over NL*NDT*DI
    int k = (int)(i & (DI-1));
    int n = (int)((i >> 9) % NDT);
    int l = (int)(i / ((size_t)NDT*DI));
    const float* xwl = xw + (size_t)l*48*DI;
    float v;
    if (n < DI) {
        const float* dr = dtw + ((size_t)l*DI + n)*DR;
        v = 0.f;
        #pragma unroll
        for (int r = 0; r < DR; r++) v += dr[r] * xwl[(size_t)r*DI + k];
    } else {
        v = xwl[(size_t)(16 + n - DI)*DI + k];
    }
    g_wall[i] = v;
}

// ---------------------------------------------------------------------------
// residual += h (or res = h when first); hn = rmsnorm(res) * w
// ---------------------------------------------------------------------------
__global__ void norm_k(const float* __restrict__ w, int first) {
    int row = blockIdx.x, t = threadIdx.x;
    size_t i = (size_t)row*DM + t;
    float v = g_h[i];
    if (!first) v += g_res[i];
    g_res[i] = v;
    float ss = v*v;
    #pragma unroll
    for (int o = 16; o > 0; o >>= 1) ss += __shfl_xor_sync(0xffffffffu, ss, o);
    __shared__ float red[8];
    __shared__ float s_scale;
    if ((t & 31) == 0) red[t >> 5] = ss;
    __syncthreads();
    if (t == 0) {
        float tot = 0.f;
        #pragma unroll
        for (int k = 0; k < 8; k++) tot += red[k];
        s_scale = rsqrtf(tot * (1.f/DM) + 1e-5f);
    }
    __syncthreads();
    g_hn[i] = v * s_scale * w[t];
}

// ---------------------------------------------------------------------------
// TF32 tensor-core GEMM: C[M,N] = A[M,K] @ W[N,K]^T
// 128x128 tile, BK=16, 256 threads (8 warps, 4x2), warp tile 32x64.
// MODE 0: plain float2 store to C.
// MODE 2: cols <512 -> g_dt softplus(+bias); cols 512..N -> g_dbc.
// ---------------------------------------------------------------------------
#define TFS 136
template<int MODE>
__global__ __launch_bounds__(256)
void tgemm_k(const float* __restrict__ A, int lda,
             const float* __restrict__ W,
             float* __restrict__ C, int ldc,
             int N, int K, const float* __restrict__ bias) {
    __shared__ uint32_t As[16][TFS];
    __shared__ uint32_t Ws[16][TFS];
    const int tid  = threadIdx.x;
    const int lane = tid & 31, warp = tid >> 5;
    const int wm = warp >> 1, wn = warp & 1;
    const int lg = lane >> 2, lt = lane & 3;
    const int m0 = blockIdx.y * 128, n0 = blockIdx.x * 128;
    const int ar = tid >> 2, ac = (tid & 3) * 4;

    float acc[2][8][4];
    #pragma unroll
    for (int mt = 0; mt < 2; mt++)
        #pragma unroll
        for (int nt = 0; nt < 8; nt++)
            #pragma unroll
            for (int q = 0; q < 4; q++) acc[mt][nt][q] = 0.f;

    float4 av0, av1, wv0, wv1;
    // prologue loads (k0 = 0)
    av0 = *(const float4*)(A + (size_t)(m0+ar)*lda + ac);
    av1 = *(const float4*)(A + (size_t)(m0+ar+64)*lda + ac);
    wv0 = (n0+ar    < N) ? *(const float4*)(W + (size_t)(n0+ar   )*K + ac)
                         : make_float4(0.f,0.f,0.f,0.f);
    wv1 = (n0+ar+64 < N) ? *(const float4*)(W + (size_t)(n0+ar+64)*K + ac)
                         : make_float4(0.f,0.f,0.f,0.f);

    for (int k0 = 0; k0 < K; k0 += 16) {
        __syncthreads();
        As[ac+0][ar]    = f2tf(av0.x); As[ac+1][ar]    = f2tf(av0.y);
        As[ac+2][ar]    = f2tf(av0.z); As[ac+3][ar]    = f2tf(av0.w);
        As[ac+0][ar+64] = f2tf(av1.x); As[ac+1][ar+64] = f2tf(av1.y);
        As[ac+2][ar+64] = f2tf(av1.z); As[ac+3][ar+64] = f2tf(av1.w);
        Ws[ac+0][ar]    = f2tf(wv0.x); Ws[ac+1][ar]    = f2tf(wv0.y);
        Ws[ac+2][ar]    = f2tf(wv0.z); Ws[ac+3][ar]    = f2tf(wv0.w);
        Ws[ac+0][ar+64] = f2tf(wv1.x); Ws[ac+1][ar+64] = f2tf(wv1.y);
        Ws[ac+2][ar+64] = f2tf(wv1.z); Ws[ac+3][ar+64] = f2tf(wv1.w);
        __syncthreads();

        int kn = k0 + 16;
        if (kn < K) {   // prefetch next tile, overlapped with MMAs below
            av0 = *(const float4*)(A + (size_t)(m0+ar)*lda + kn + ac);
            av1 = *(const float4*)(A + (size_t)(m0+ar+64)*lda + kn + ac);
            wv0 = (n0+ar    < N) ? *(const float4*)(W + (size_t)(n0+ar   )*K + kn + ac)
                                 : make_float4(0.f,0.f,0.f,0.f);
            wv1 = (n0+ar+64 < N) ? *(const float4*)(W + (size_t)(n0+ar+64)*K + kn + ac)
                                 : make_float4(0.f,0.f,0.f,0.f);
        }

        #pragma unroll
        for (int ks = 0; ks < 16; ks += 8) {
            uint32_t a[2][4], b[8][2];
            #pragma unroll
            for (int mt = 0; mt < 2; mt++) {
                int mb = wm*32 + mt*16;
                a[mt][0] = As[ks+lt  ][mb+lg];
                a[mt][1] = As[ks+lt  ][mb+lg+8];
                a[mt][2] = As[ks+lt+4][mb+lg];
                a[mt][3] = As[ks+lt+4][mb+lg+8];
            }
            #pragma unroll
            for (int nt = 0; nt < 8; nt++) {
                int nb = wn*64 + nt*8;
                b[nt][0] = Ws[ks+lt  ][nb+lg];
                b[nt][1] = Ws[ks+lt+4][nb+lg];
            }
            #pragma unroll
            for (int mt = 0; mt < 2; mt++)
                #pragma unroll
                for (int nt = 0; nt < 8; nt++)
                    mma8(acc[mt][nt], a[mt], b[nt]);
        }
    }

    #pragma unroll
    for (int mt = 0; mt < 2; mt++) {
        int m = m0 + wm*32 + mt*16 + lg;
        #pragma unroll
        for (int nt = 0; nt < 8; nt++) {
            int n = n0 + wn*64 + nt*8 + lt*2;
            float c0 = acc[mt][nt][0], c1 = acc[mt][nt][1];
            float c2 = acc[mt][nt][2], c3 = acc[mt][nt][3];
            if (MODE == 0) {
                if (n < N) {
                    *(float2*)(C + (size_t)m*ldc + n)     = make_float2(c0, c1);
                    *(float2*)(C + (size_t)(m+8)*ldc + n) = make_float2(c2, c3);
                }
            } else { // MODE 2
                if (n < DI) {
                    float b0 = bias[n], b1 = bias[n+1];
                    g_dt[(size_t)m*DI + n]       = softplusf(c0 + b0);
                    g_dt[(size_t)m*DI + n+1]     = softplusf(c1 + b1);
                    g_dt[(size_t)(m+8)*DI + n]   = softplusf(c2 + b0);
                    g_dt[(size_t)(m+8)*DI + n+1] = softplusf(c3 + b1);
                } else if (n < N) {
                    int j = n - DI;
                    *(float2*)(g_dbc + (size_t)m*32 + j)     = make_float2(c0, c1);
                    *(float2*)(g_dbc + (size_t)(m+8)*32 + j) = make_float2(c2, c3);
                }
            }
        }
    }
}

// ---------------------------------------------------------------------------
// Fallback SIMT GEMM (lm_head only): C[M,N] = A[M,K] @ W[N,K]^T
// ---------------------------------------------------------------------------
__global__ __launch_bounds__(256)
void gemm_k(const float* __restrict__ A, int lda,
            const float* __restrict__ W,
            float* __restrict__ C, int ldc,
            int N, int K) {
    __shared__ float As[8][128];
    __shared__ float Ws[8][128];
    const int tid  = threadIdx.x;
    const int m0   = blockIdx.y * 128;
    const int irow = tid >> 1;
    const int icol = (tid & 1) * 4;
    const int trow = tid >> 4;
    const int tcol = tid & 15;

    float acc[8][8];
    #pragma unroll
    for (int i = 0; i < 8; i++)
        #pragma unroll
        for (int j = 0; j < 8; j++) acc[i][j] = 0.f;

    for (int k0 = 0; k0 < K; k0 += 8) {
        float4 av = *reinterpret_cast<const float4*>(
            A + (size_t)(m0 + irow)*lda + k0 + icol);
        As[icol+0][irow] = av.x; As[icol+1][irow] = av.y;
        As[icol+2][irow] = av.z; As[icol+3][irow] = av.w;
        float4 wv = make_float4(0.f,0.f,0.f,0.f);
        if (irow < N)
            wv = *reinterpret_cast<const float4*>(W + (size_t)irow*K + k0 + icol);
        Ws[icol+0][irow] = wv.x; Ws[icol+1][irow] = wv.y;
        Ws[icol+2][irow] = wv.z; Ws[icol+3][irow] = wv.w;
        __syncthreads();
        #pragma unroll
        for (int kk = 0; kk < 8; kk++) {
            float a[8], b[8];
            #pragma unroll
            for (int i = 0; i < 8; i++) a[i] = As[kk][trow*8 + i];
            #pragma unroll
            for (int j = 0; j < 8; j++) b[j] = Ws[kk][tcol*8 + j];
            #pragma unroll
            for (int i = 0; i < 8; i++)
                #pragma unroll
                for (int j = 0; j < 8; j++) acc[i][j] += a[i]*b[j];
        }
        __syncthreads();
    }
    #pragma unroll
    for (int i = 0; i < 8; i++) {
        int m = m0 + trow*8 + i;
        #pragma unroll
        for (int j = 0; j < 8; j++) {
            int n = tcol*8 + j;
            if (n < N) C[(size_t)m*ldc + n] = acc[i][j];
        }
    }
}

// ---------------------------------------------------------------------------
// Depthwise causal conv (width 4) + bias + silu. 4 outputs/thread.
// ---------------------------------------------------------------------------
__global__ void conv_k(const float* __restrict__ cw,
                       const float* __restrict__ cb) {
    int rg = blockIdx.x;            // ROWS/4 groups of 4 consecutive l
    int b  = rg >> 9;
    int l0 = (rg & 511) * 4;
    int tid = threadIdx.x;
    #pragma unroll
    for (int dd = 0; dd < 2; dd++) {
        int d = tid + dd*256;
        float w0 = cw[d*4], w1 = cw[d*4+1], w2 = cw[d*4+2], w3 = cw[d*4+3];
        float bia = cb[d];
        float xv[7];
        #pragma unroll
        for (int j = 0; j < 7; j++) {
            int l = l0 - 3 + j;
            xv[j] = (l >= 0) ? g_xz[(size_t)((b<<11) + l)*(2*DI) + d] : 0.f;
        }
        #pragma unroll
        for (int i = 0; i < 4; i++) {
            float acc = bia + w0*xv[i] + w1*xv[i+1] + w2*xv[i+2] + w3*xv[i+3];
            g_xc[(size_t)((b<<11) + l0 + i)*DI + d] = siluf(acc);
        }
    }
}

// ---------------------------------------------------------------------------
// Selective scan, chunked 2-pass. B/C staged in shared memory.
// dA_s = exp(dt*A_s); with A_s = (s+1)*A_0 (S4D-real) -> dA_s = E^(s+1).
// ---------------------------------------------------------------------------
__device__ __forceinline__ void compute_dA(float dA[DS], const float A[DS],
                                           float dtv, bool fast) {
    if (fast) {
        float E  = __expf(A[0]*dtv);
        float e2 = E*E, e4 = e2*e2, e8 = e4*e4;
        dA[0]=E;        dA[1]=e2;        dA[2]=e2*E;        dA[3]=e4;
        dA[4]=e4*E;     dA[5]=e4*e2;     dA[6]=e4*e2*E;     dA[7]=e8;
        dA[8]=e8*E;     dA[9]=e8*e2;     dA[10]=e8*e2*E;    dA[11]=e8*e4;
        dA[12]=e8*e4*E; dA[13]=e8*e4*e2; dA[14]=e8*e4*e2*E; dA[15]=e8*e8;
    } else {
        #pragma unroll
        for (int s = 0; s < DS; s++) dA[s] = __expf(A[s]*dtv);
    }
}

__device__ __forceinline__ void load_A(const float* __restrict__ A_log,
                                       int d, float A[DS], bool& fast) {
    #pragma unroll
    for (int s = 0; s < DS; s++) A[s] = -__expf(A_log[d*DS + s]);
    fast = true;
    #pragma unroll
    for (int s = 1; s < DS; s++)
        fast = fast && (fabsf(A[s] - (float)(s+1)*A[0]) <= 1e-3f*fabsf(A[s]));
}

// grid: BB*NC*2 blocks of 256; block covers 256 d-channels of one (b, chunk)
__global__ __launch_bounds__(256)
void scan1_k(const float* __restrict__ A_log) {
    __shared__ float sBC[CT][32];
    int bi = blockIdx.x;
    int b     = bi >> 6;
    int chunk = (bi >> 1) & (NC-1);
    int d     = ((bi & 1) << 8) + threadIdx.x;
    int base  = b*LL + chunk*CT;

    for (int i = threadIdx.x; i < CT*8; i += 256) {
        int r = i >> 3, c = (i & 7) * 4;
        *(float4*)&sBC[r][c] = *(const float4*)(g_dbc + (size_t)(base+r)*32 + c);
    }
    __syncthreads();

    float A[DS]; bool fast;
    load_A(A_log, d, A, fast);

    float h[DS], ap[DS];
    #pragma unroll
    for (int s = 0; s < DS; s++) { h[s] = 0.f; ap[s] = 1.f; }
    float sumdt = 0.f;

    float dtv = g_dt[(size_t)base*DI + d];
    float xv  = g_xc[(size_t)base*DI + d];
    for (int t = 0; t < CT; t++) {
        float dtn = 0.f, xn = 0.f;
        if (t + 1 < CT) {
            dtn = g_dt[(size_t)(base+t+1)*DI + d];
            xn  = g_xc[(size_t)(base+t+1)*DI + d];
        }
        float c = dtv * xv;
        float dA[DS];
        compute_dA(dA, A, dtv, fast);
        sumdt += dtv;
        if (!fast) {
            #pragma unroll
            for (int s = 0; s < DS; s++) ap[s] *= dA[s];
        }
        #pragma unroll
        for (int s = 0; s < DS; s++)
            h[s] = dA[s]*h[s] + c*sBC[t][s];
        dtv = dtn; xv = xn;
    }
    if (fast) compute_dA(ap, A, sumdt, true);

    size_t idx0 = ((size_t)(b*DI + d)*DS)*NC + chunk;
    #pragma unroll
    for (int s = 0; s < DS; s++) {
        g_ap[idx0 + (size_t)s*NC] = ap[s];
        g_hl[idx0 + (size_t)s*NC] = h[s];
    }
}

// serial scan across NC chunk carries: one thread per (b,d,s)
__global__ void combine_k() {
    int i = blockIdx.x*256 + threadIdx.x;     // 0..BB*DI*DS
    size_t base = (size_t)i * NC;
    float h = 0.f;
    #pragma unroll
    for (int c = 0; c < NC; c++) {
        g_hi[base + c] = h;
        h = g_ap[base + c]*h + g_hl[base + c];
    }
}

__global__ __launch_bounds__(256)
void scan2_k(const float* __restrict__ A_log,
             const float* __restrict__ Dp) {
    __shared__ float sBC[CT][32];
    int bi = blockIdx.x;
    int b     = bi >> 6;
    int chunk = (bi >> 1) & (NC-1);
    int d     = ((bi & 1) << 8) + threadIdx.x;
    int base  = b*LL + chunk*CT;

    for (int i = threadIdx.x; i < CT*8; i += 256) {
        int r = i >> 3, c = (i & 7) * 4;
        *(float4*)&sBC[r][c] = *(const float4*)(g_dbc + (size_t)(base+r)*32 + c);
    }
    __syncthreads();

    float A[DS]; bool fast;
    load_A(A_log, d, A, fast);
    float Dd = Dp[d];

    size_t idx0 = ((size_t)(b*DI + d)*DS)*NC + chunk;
    float h[DS];
    #pragma unroll
    for (int s = 0; s < DS; s++) h[s] = g_hi[idx0 + (size_t)s*NC];

    float dtv = g_dt[(size_t)base*DI + d];
    float xv  = g_xc[(size_t)base*DI + d];
    for (int t = 0; t < CT; t++) {
        float dtn = 0.f, xn = 0.f;
        if (t + 1 < CT) {
            dtn = g_dt[(size_t)(base+t+1)*DI + d];
            xn  = g_xc[(size_t)(base+t+1)*DI + d];
        }
        float c = dtv * xv;
        float dA[DS];
        compute_dA(dA, A, dtv, fast);
        float acc = 0.f;
        #pragma unroll
        for (int s = 0; s < DS; s++) {
            h[s] = dA[s]*h[s] + c*sBC[t][s];
            acc += h[s]*sBC[t][16+s];
        }
        size_t row = base + t;
        float zv = g_xz[row*(2*DI) + DI + d];
        g_y[row*DI + d] = (acc + Dd*xv) * siluf(zv);
        dtv = dtn; xv = xn;
    }
}

// ---------------------------------------------------------------------------
// Host side
// ---------------------------------------------------------------------------
extern "C" void kernel_launch(void* const* d_in, const int* in_sizes, int n_in,
                              void* d_out, int out_size) {
    const int*   ids  = (const int*)  d_in[0];
    const float* emb  = (const float*)d_in[1];
    const float* inw  = (const float*)d_in[2];   // (NL, 2*DI, DM)
    const float* cw   = (const float*)d_in[3];   // (NL, DI, 4)
    const float* cb   = (const float*)d_in[4];   // (NL, DI)
    const float* xw   = (const float*)d_in[5];   // (NL, 48, DI)
    const float* dtw  = (const float*)d_in[6];   // (NL, DI, DR)
    const float* dtb  = (const float*)d_in[7];   // (NL, DI)
    const float* alog = (const float*)d_in[8];   // (NL, DI, DS)
    const float* Dp   = (const float*)d_in[9];   // (NL, DI)
    const float* ow   = (const float*)d_in[10];  // (NL, DM, DI)
    const float* nw   = (const float*)d_in[11];  // (NL, DM)
    const float* nfw  = (const float*)d_in[12];  // (DM)
    const float* lmw  = (const float*)d_in[13];  // (20, DM)
    float* out = (float*)d_out;

    float *p_hn, *p_xz, *p_xc, *p_y, *p_h, *p_wall;
    cudaGetSymbolAddress((void**)&p_hn,   g_hn);
    cudaGetSymbolAddress((void**)&p_xz,   g_xz);
    cudaGetSymbolAddress((void**)&p_xc,   g_xc);
    cudaGetSymbolAddress((void**)&p_y,    g_y);
    cudaGetSymbolAddress((void**)&p_h,    g_h);
    cudaGetSymbolAddress((void**)&p_wall, g_wall);

    embed_k<<<ROWS, DM>>>(ids, emb);
    wdt_k<<<NL*NDT*DI/256, 256>>>(xw, dtw);

    for (int l = 0; l < NL; l++) {
        norm_k<<<ROWS, DM>>>(nw + (size_t)l*DM, l == 0);

        // in_proj: (4096,256) x (1024,256)^T -> xz (4096,1024)
        tgemm_k<0><<<dim3(8, 32), 256>>>(p_hn, DM, inw + (size_t)l*2*DI*DM,
                                         p_xz, 2*DI, 2*DI, DM, nullptr);
        // depthwise conv + silu
        conv_k<<<ROWS/4, 256>>>(cw + (size_t)l*DI*4, cb + (size_t)l*DI);

        // fused dt|B|C: (4096,512) x (544,512)^T
        tgemm_k<2><<<dim3(5, 32), 256>>>(p_xc, DI, p_wall + (size_t)l*NDT*DI,
                                         nullptr, 0, NDT, DI, dtb + (size_t)l*DI);
        // chunked selective scan
        scan1_k<<<BB*NC*2, 256>>>(alog + (size_t)l*DI*DS);
        combine_k<<<BB*DI*DS/256, 256>>>();
        scan2_k<<<BB*NC*2, 256>>>(alog + (size_t)l*DI*DS, Dp + (size_t)l*DI);

        // out_proj: (4096,512) x (256,512)^T -> h (4096,256)
        tgemm_k<0><<<dim3(2, 32), 256>>>(p_y, DI, ow + (size_t)l*DM*DI,
                                         p_h, DM, DM, DI, nullptr);
    }

    // final residual + norm + lm_head
    norm_k<<<ROWS, DM>>>(nfw, 0);
    gemm_k<<<dim3(1, 32), 256>>>(p_hn, DM, lmw, out, 20, 20, DM);
}

// round 6
// speedup vs baseline: 2.0644x; 1.0585x over previous
#include <cuda_runtime.h>
#include <cuda_bf16.h>
#include <cstdint>

// ---------------------------------------------------------------------------
// Problem constants
// ---------------------------------------------------------------------------
#define BB      2
#define LL      2048
#define ROWS    (BB*LL)        // 4096 tokens
#define DM      256            // d_model
#define DI      512            // d_inner
#define DS      16             // d_state
#define DR      16             // dt_rank
#define NL      16             // layers
#define NC      32             // scan chunks per sequence
#define CT      (LL/NC)        // 64 steps per chunk
#define NDT     544            // fused dt|B|C GEMM width (512 + 32)
#define LOG2E   1.44269504f

// ---------------------------------------------------------------------------
// Scratch (static device allocations — no cudaMalloc allowed)
// ---------------------------------------------------------------------------
__device__ float g_h  [ROWS*DM];     // block output / embedding
__device__ float g_res[ROWS*DM];     // residual stream
__device__ float g_hn [ROWS*DM];     // normed input
__device__ float g_xz [ROWS*2*DI];   // in_proj output (x | silu(z))
__device__ float g_xc [ROWS*DI];     // conv+silu output
__device__ float g_dbc[ROWS*32];     // B | C per token
__device__ float g_dt [ROWS*DI];     // softplus(dt)
__device__ float g_e  [ROWS*DI];     // exp(-dt)
__device__ float g_y  [ROWS*DI];     // scan output * silu(z)
__device__ float g_ap [BB*DI*DS*NC]; // chunk prod(dA)
__device__ float g_hl [BB*DI*DS*NC]; // chunk local h final
__device__ float g_hi [BB*DI*DS*NC]; // chunk initial h
__device__ float g_wall[NL*NDT*DI];  // fused (W_dt | xw_B | xw_C) weights

// ---------------------------------------------------------------------------
// FMA-pipe fast math (avoids MUFU bottleneck: chip MUFU = 74 ops/cyc)
// exp2-based exp with degree-6 poly, rel err ~1.2e-7.
// ---------------------------------------------------------------------------
__device__ __forceinline__ float fexp2(float x) {
    x = fminf(fmaxf(x, -125.f), 127.f);
    float t = x + 12582912.f;              // 1.5 * 2^23 round trick
    int   i = __float_as_int(t) - 0x4B400000;   // rint(x)
    float f = x - (t - 12582912.f);             // frac in [-0.5, 0.5]
    float p = 1.54035304e-4f;
    p = fmaf(p, f, 1.33335581e-3f);
    p = fmaf(p, f, 9.61812911e-3f);
    p = fmaf(p, f, 5.55041087e-2f);
    p = fmaf(p, f, 2.40226507e-1f);
    p = fmaf(p, f, 6.93147181e-1f);
    p = fmaf(p, f, 1.0f);
    return p * __int_as_float((i + 127) << 23);
}
__device__ __forceinline__ float fsilu(float v) {
    return __fdividef(v, 1.f + fexp2(-LOG2E * v));
}
__device__ __forceinline__ float fsoftplus(float v) {
    if (v > 15.f) return v;
    return log1pf(fexp2(LOG2E * v));
}
__device__ __forceinline__ uint32_t f2tf(float f) {
    uint32_t u; asm("cvt.rna.tf32.f32 %0, %1;" : "=r"(u) : "f"(f)); return u;
}
__device__ __forceinline__ void mma8(float* c, const uint32_t* a, const uint32_t* b) {
    asm volatile(
        "mma.sync.aligned.m16n8k8.row.col.f32.tf32.tf32.f32 "
        "{%0,%1,%2,%3}, {%4,%5,%6,%7}, {%8,%9}, {%0,%1,%2,%3};"
        : "+f"(c[0]), "+f"(c[1]), "+f"(c[2]), "+f"(c[3])
        : "r"(a[0]), "r"(a[1]), "r"(a[2]), "r"(a[3]), "r"(b[0]), "r"(b[1]));
}

// ---------------------------------------------------------------------------
// Embedding gather
// ---------------------------------------------------------------------------
__global__ void embed_k(const int* __restrict__ ids,
                        const float* __restrict__ emb) {
    int row = blockIdx.x, t = threadIdx.x;
    g_h[(size_t)row*DM + t] = emb[(size_t)ids[row]*DM + t];
}

// ---------------------------------------------------------------------------
// Fused weight precompute: W_dt = dtw @ xw[0:16] ; rows 512.. = xw B/C rows
// ---------------------------------------------------------------------------
__global__ void wdt_k(const float* __restrict__ xw,
                      const float* __restrict__ dtw) {
    size_t i = (size_t)blockIdx.x*256 + threadIdx.x;
    int k = (int)(i & (DI-1));
    int n = (int)((i >> 9) % NDT);
    int l = (int)(i / ((size_t)NDT*DI));
    const float* xwl = xw + (size_t)l*48*DI;
    float v;
    if (n < DI) {
        const float* dr = dtw + ((size_t)l*DI + n)*DR;
        v = 0.f;
        #pragma unroll
        for (int r = 0; r < DR; r++) v += dr[r] * xwl[(size_t)r*DI + k];
    } else {
        v = xwl[(size_t)(16 + n - DI)*DI + k];
    }
    g_wall[i] = v;
}

// ---------------------------------------------------------------------------
// residual += h (or res = h when first); hn = rmsnorm(res) * w
// ---------------------------------------------------------------------------
__global__ void norm_k(const float* __restrict__ w, int first) {
    int row = blockIdx.x, t = threadIdx.x;
    size_t i = (size_t)row*DM + t;
    float v = g_h[i];
    if (!first) v += g_res[i];
    g_res[i] = v;
    float ss = v*v;
    #pragma unroll
    for (int o = 16; o > 0; o >>= 1) ss += __shfl_xor_sync(0xffffffffu, ss, o);
    __shared__ float red[8];
    __shared__ float s_scale;
    if ((t & 31) == 0) red[t >> 5] = ss;
    __syncthreads();
    if (t == 0) {
        float tot = 0.f;
        #pragma unroll
        for (int k = 0; k < 8; k++) tot += red[k];
        s_scale = rsqrtf(tot * (1.f/DM) + 1e-5f);
    }
    __syncthreads();
    g_hn[i] = v * s_scale * w[t];
}

// ---------------------------------------------------------------------------
// TF32 tensor-core GEMM: C[M,N] = A[M,K] @ W[N,K]^T
// BMx128 tile, BK=16, BM*2 threads, warp tile 32x64.
// Smem layout: per row 16 u32, k-permuted (slot=(k&3)*4+(k>>2)) and
// 16B-chunk XOR-swizzled by (row>>1)&3 -> both STS and LDS.128 conflict-free,
// and one LDS.128 yields a thread's 4 k-values covering both ks-steps.
// MODE 0: plain store. MODE 1: silu on cols >= DI (in_proj z half).
// MODE 2: cols < DI -> g_dt softplus(+bias) and g_e=exp(-dt); else g_dbc.
// ---------------------------------------------------------------------------
template<int MODE, int BM>
__global__ __launch_bounds__(BM*2)
void tgemm_k(const float* __restrict__ A, int lda,
             const float* __restrict__ W,
             float* __restrict__ C, int ldc,
             int N, int K, const float* __restrict__ bias) {
    constexpr int TH  = BM*2;
    constexpr int RQ  = TH/4;       // rows covered per load batch
    constexpr int AIT = BM/RQ;      // = 2
    constexpr int WIT = 128/RQ;     // 2 (BM=128) or 4 (BM=64)
    __shared__ uint32_t As[BM*16];
    __shared__ uint32_t Ws[128*16];
    const int tid  = threadIdx.x;
    const int lane = tid & 31, warp = tid >> 5;
    const int wm = warp >> 1, wn = warp & 1;
    const int lg = lane >> 2, lt = lane & 3;
    const int m0 = blockIdx.y * BM, n0 = blockIdx.x * 128;
    const int ar = tid >> 2, aj = tid & 3;
    const int ac = aj * 4;

    float acc[2][8][4];
    #pragma unroll
    for (int mt = 0; mt < 2; mt++)
        #pragma unroll
        for (int nt = 0; nt < 8; nt++)
            #pragma unroll
            for (int q = 0; q < 4; q++) acc[mt][nt][q] = 0.f;

    float4 av[AIT], wv[WIT];
    // prologue global loads (k0 = 0)
    #pragma unroll
    for (int i = 0; i < AIT; i++)
        av[i] = *(const float4*)(A + (size_t)(m0 + ar + i*RQ)*lda + ac);
    #pragma unroll
    for (int i = 0; i < WIT; i++) {
        int r = n0 + ar + i*RQ;
        wv[i] = (r < N) ? *(const float4*)(W + (size_t)r*K + ac)
                        : make_float4(0.f,0.f,0.f,0.f);
    }

    for (int k0 = 0; k0 < K; k0 += 16) {
        __syncthreads();
        #pragma unroll
        for (int i = 0; i < AIT; i++) {
            int r = ar + i*RQ;
            int sw = (r >> 1) & 3;
            uint32_t* dst = As + r*16 + aj;
            dst[(0^sw)*4] = f2tf(av[i].x);
            dst[(1^sw)*4] = f2tf(av[i].y);
            dst[(2^sw)*4] = f2tf(av[i].z);
            dst[(3^sw)*4] = f2tf(av[i].w);
        }
        #pragma unroll
        for (int i = 0; i < WIT; i++) {
            int r = ar + i*RQ;
            int sw = (r >> 1) & 3;
            uint32_t* dst = Ws + r*16 + aj;
            dst[(0^sw)*4] = f2tf(wv[i].x);
            dst[(1^sw)*4] = f2tf(wv[i].y);
            dst[(2^sw)*4] = f2tf(wv[i].z);
            dst[(3^sw)*4] = f2tf(wv[i].w);
        }
        __syncthreads();

        int kn = k0 + 16;
        if (kn < K) {   // prefetch next tile; LDGs overlap the MMAs below
            #pragma unroll
            for (int i = 0; i < AIT; i++)
                av[i] = *(const float4*)(A + (size_t)(m0 + ar + i*RQ)*lda + kn + ac);
            #pragma unroll
            for (int i = 0; i < WIT; i++) {
                int r = n0 + ar + i*RQ;
                wv[i] = (r < N) ? *(const float4*)(W + (size_t)r*K + kn + ac)
                                : make_float4(0.f,0.f,0.f,0.f);
            }
        }

        const uint4* As4 = reinterpret_cast<const uint4*>(As);
        const uint4* Ws4 = reinterpret_cast<const uint4*>(Ws);
        uint4 qa[2][2], qb[8];
        #pragma unroll
        for (int mt = 0; mt < 2; mt++) {
            int r0 = wm*32 + mt*16 + lg;
            int r1 = r0 + 8;
            qa[mt][0] = As4[r0*4 + (lt ^ ((r0 >> 1) & 3))];
            qa[mt][1] = As4[r1*4 + (lt ^ ((r1 >> 1) & 3))];
        }
        #pragma unroll
        for (int nt = 0; nt < 8; nt++) {
            int r = wn*64 + nt*8 + lg;
            qb[nt] = Ws4[r*4 + (lt ^ ((r >> 1) & 3))];
        }
        #pragma unroll
        for (int mt = 0; mt < 2; mt++) {
            uint32_t a0[4] = {qa[mt][0].x, qa[mt][1].x, qa[mt][0].y, qa[mt][1].y};
            uint32_t a1[4] = {qa[mt][0].z, qa[mt][1].z, qa[mt][0].w, qa[mt][1].w};
            #pragma unroll
            for (int nt = 0; nt < 8; nt++) {
                uint32_t b0[2] = {qb[nt].x, qb[nt].y};
                uint32_t b1[2] = {qb[nt].z, qb[nt].w};
                mma8(acc[mt][nt], a0, b0);
                mma8(acc[mt][nt], a1, b1);
            }
        }
    }

    #pragma unroll
    for (int mt = 0; mt < 2; mt++) {
        int m = m0 + wm*32 + mt*16 + lg;
        #pragma unroll
        for (int nt = 0; nt < 8; nt++) {
            int n = n0 + wn*64 + nt*8 + lt*2;
            float c0 = acc[mt][nt][0], c1 = acc[mt][nt][1];
            float c2 = acc[mt][nt][2], c3 = acc[mt][nt][3];
            if (MODE == 0 || MODE == 1) {
                if (MODE == 1 && n0 >= DI) {   // z half: pre-apply silu
                    c0 = fsilu(c0); c1 = fsilu(c1);
                    c2 = fsilu(c2); c3 = fsilu(c3);
                }
                if (n < N) {
                    *(float2*)(C + (size_t)m*ldc + n)     = make_float2(c0, c1);
                    *(float2*)(C + (size_t)(m+8)*ldc + n) = make_float2(c2, c3);
                }
            } else { // MODE 2
                if (n < DI) {
                    float b0 = bias[n], b1 = bias[n+1];
                    float d00 = fsoftplus(c0 + b0), d01 = fsoftplus(c1 + b1);
                    float d10 = fsoftplus(c2 + b0), d11 = fsoftplus(c3 + b1);
                    *(float2*)(g_dt + (size_t)m*DI + n)     = make_float2(d00, d01);
                    *(float2*)(g_dt + (size_t)(m+8)*DI + n) = make_float2(d10, d11);
                    *(float2*)(g_e + (size_t)m*DI + n) =
                        make_float2(fexp2(-LOG2E*d00), fexp2(-LOG2E*d01));
                    *(float2*)(g_e + (size_t)(m+8)*DI + n) =
                        make_float2(fexp2(-LOG2E*d10), fexp2(-LOG2E*d11));
                } else if (n < N) {
                    int j = n - DI;
                    *(float2*)(g_dbc + (size_t)m*32 + j)     = make_float2(c0, c1);
                    *(float2*)(g_dbc + (size_t)(m+8)*32 + j) = make_float2(c2, c3);
                }
            }
        }
    }
}

// ---------------------------------------------------------------------------
// SIMT GEMM (lm_head only): C[M,N] = A[M,K] @ W[N,K]^T
// ---------------------------------------------------------------------------
__global__ __launch_bounds__(256)
void gemm_k(const float* __restrict__ A, int lda,
            const float* __restrict__ W,
            float* __restrict__ C, int ldc,
            int N, int K) {
    __shared__ float As[8][128];
    __shared__ float Ws[8][128];
    const int tid  = threadIdx.x;
    const int m0   = blockIdx.y * 128;
    const int irow = tid >> 1;
    const int icol = (tid & 1) * 4;
    const int trow = tid >> 4;
    const int tcol = tid & 15;

    float acc[8][8];
    #pragma unroll
    for (int i = 0; i < 8; i++)
        #pragma unroll
        for (int j = 0; j < 8; j++) acc[i][j] = 0.f;

    for (int k0 = 0; k0 < K; k0 += 8) {
        float4 av = *reinterpret_cast<const float4*>(
            A + (size_t)(m0 + irow)*lda + k0 + icol);
        As[icol+0][irow] = av.x; As[icol+1][irow] = av.y;
        As[icol+2][irow] = av.z; As[icol+3][irow] = av.w;
        float4 wv = make_float4(0.f,0.f,0.f,0.f);
        if (irow < N)
            wv = *reinterpret_cast<const float4*>(W + (size_t)irow*K + k0 + icol);
        Ws[icol+0][irow] = wv.x; Ws[icol+1][irow] = wv.y;
        Ws[icol+2][irow] = wv.z; Ws[icol+3][irow] = wv.w;
        __syncthreads();
        #pragma unroll
        for (int kk = 0; kk < 8; kk++) {
            float a[8], b[8];
            #pragma unroll
            for (int i = 0; i < 8; i++) a[i] = As[kk][trow*8 + i];
            #pragma unroll
            for (int j = 0; j < 8; j++) b[j] = Ws[kk][tcol*8 + j];
            #pragma unroll
            for (int i = 0; i < 8; i++)
                #pragma unroll
                for (int j = 0; j < 8; j++) acc[i][j] += a[i]*b[j];
        }
        __syncthreads();
    }
    #pragma unroll
    for (int i = 0; i < 8; i++) {
        int m = m0 + trow*8 + i;
        #pragma unroll
        for (int j = 0; j < 8; j++) {
            int n = tcol*8 + j;
            if (n < N) C[(size_t)m*ldc + n] = acc[i][j];
        }
    }
}

// ---------------------------------------------------------------------------
// Depthwise causal conv (width 4) + bias + silu. 4 outputs/thread.
// ---------------------------------------------------------------------------
__global__ void conv_k(const float* __restrict__ cw,
                       const float* __restrict__ cb) {
    int rg = blockIdx.x;            // ROWS/4 groups of 4 consecutive l
    int b  = rg >> 9;
    int l0 = (rg & 511) * 4;
    int tid = threadIdx.x;
    #pragma unroll
    for (int dd = 0; dd < 2; dd++) {
        int d = tid + dd*256;
        float w0 = cw[d*4], w1 = cw[d*4+1], w2 = cw[d*4+2], w3 = cw[d*4+3];
        float bia = cb[d];
        float xv[7];
        #pragma unroll
        for (int j = 0; j < 7; j++) {
            int l = l0 - 3 + j;
            xv[j] = (l >= 0) ? g_xz[(size_t)((b<<11) + l)*(2*DI) + d] : 0.f;
        }
        #pragma unroll
        for (int i = 0; i < 4; i++) {
            float acc = bia + w0*xv[i] + w1*xv[i+1] + w2*xv[i+2] + w3*xv[i+3];
            g_xc[(size_t)((b<<11) + l0 + i)*DI + d] = fsilu(acc);
        }
    }
}

// ---------------------------------------------------------------------------
// Selective scan, chunked 2-pass. MUFU-free fast path:
// E = exp(-dt) comes precomputed from the dtBC GEMM epilogue (g_e), and
// dA_s = E^(s+1) (S4D-real: A_s = -(s+1)); prod(dA) via running prod(E).
// ---------------------------------------------------------------------------
__device__ __forceinline__ void powers16(float dA[DS], float E) {
    float e2 = E*E, e4 = e2*e2, e8 = e4*e4;
    dA[0]=E;        dA[1]=e2;        dA[2]=e2*E;        dA[3]=e4;
    dA[4]=e4*E;     dA[5]=e4*e2;     dA[6]=e4*e2*E;     dA[7]=e8;
    dA[8]=e8*E;     dA[9]=e8*e2;     dA[10]=e8*e2*E;    dA[11]=e8*e4;
    dA[12]=e8*e4*E; dA[13]=e8*e4*e2; dA[14]=e8*e4*e2*E; dA[15]=e8*e8;
}

__device__ __forceinline__ void load_A(const float* __restrict__ A_log,
                                       int d, float A[DS], bool& fast) {
    #pragma unroll
    for (int s = 0; s < DS; s++) A[s] = -__expf(A_log[d*DS + s]);
    fast = fabsf(A[0] + 1.f) <= 1e-4f;
    #pragma unroll
    for (int s = 1; s < DS; s++)
        fast = fast && (fabsf(A[s] - (float)(s+1)*A[0]) <= 1e-3f*fabsf(A[s]));
}

// grid: BB*NC*2 blocks of 256; block covers 256 d-channels of one (b, chunk)
__global__ __launch_bounds__(256)
void scan1_k(const float* __restrict__ A_log) {
    __shared__ float sB[CT][16];
    int bi = blockIdx.x;
    int b     = bi >> 6;
    int chunk = (bi >> 1) & (NC-1);
    int d     = ((bi & 1) << 8) + threadIdx.x;
    int base  = b*LL + chunk*CT;

    {   // stage B columns only (slots 0..15)
        int r = threadIdx.x >> 2, c = (threadIdx.x & 3) * 4;
        *(float4*)&sB[r][c] = *(const float4*)(g_dbc + (size_t)(base+r)*32 + c);
    }
    __syncthreads();

    float A[DS]; bool fast;
    load_A(A_log, d, A, fast);

    float h[DS], ap[DS];
    #pragma unroll
    for (int s = 0; s < DS; s++) { h[s] = 0.f; ap[s] = 1.f; }
    float prodE = 1.f;

    float dtv = g_dt[(size_t)base*DI + d];
    float xv  = g_xc[(size_t)base*DI + d];
    float Ev  = g_e [(size_t)base*DI + d];
    for (int t = 0; t < CT; t++) {
        float dtn = 0.f, xn = 0.f, En = 0.f;
        if (t + 1 < CT) {
            size_t nr = (size_t)(base+t+1)*DI + d;
            dtn = g_dt[nr]; xn = g_xc[nr]; En = g_e[nr];
        }
        float c = dtv * xv;
        float dA[DS];
        if (fast) {
            powers16(dA, Ev);
            prodE *= Ev;
        } else {
            #pragma unroll
            for (int s = 0; s < DS; s++) { dA[s] = __expf(A[s]*dtv); ap[s] *= dA[s]; }
        }
        #pragma unroll
        for (int s = 0; s < DS; s++)
            h[s] = dA[s]*h[s] + c*sB[t][s];
        dtv = dtn; xv = xn; Ev = En;
    }
    if (fast) powers16(ap, prodE);

    size_t idx0 = ((size_t)(b*DI + d)*DS)*NC + chunk;
    #pragma unroll
    for (int s = 0; s < DS; s++) {
        g_ap[idx0 + (size_t)s*NC] = ap[s];
        g_hl[idx0 + (size_t)s*NC] = h[s];
    }
}

// serial scan across NC chunk carries: one thread per (b,d,s)
__global__ void combine_k() {
    int i = blockIdx.x*256 + threadIdx.x;     // 0..BB*DI*DS
    size_t base = (size_t)i * NC;
    float h = 0.f;
    #pragma unroll
    for (int c = 0; c < NC; c++) {
        g_hi[base + c] = h;
        h = g_ap[base + c]*h + g_hl[base + c];
    }
}

__global__ __launch_bounds__(256)
void scan2_k(const float* __restrict__ A_log,
             const float* __restrict__ Dp) {
    __shared__ float sBC[CT][32];
    int bi = blockIdx.x;
    int b     = bi >> 6;
    int chunk = (bi >> 1) & (NC-1);
    int d     = ((bi & 1) << 8) + threadIdx.x;
    int base  = b*LL + chunk*CT;

    for (int i = threadIdx.x; i < CT*8; i += 256) {
        int r = i >> 3, c = (i & 7) * 4;
        *(float4*)&sBC[r][c] = *(const float4*)(g_dbc + (size_t)(base+r)*32 + c);
    }
    __syncthreads();

    float A[DS]; bool fast;
    load_A(A_log, d, A, fast);
    float Dd = Dp[d];

    size_t idx0 = ((size_t)(b*DI + d)*DS)*NC + chunk;
    float h[DS];
    #pragma unroll
    for (int s = 0; s < DS; s++) h[s] = g_hi[idx0 + (size_t)s*NC];

    float dtv = g_dt[(size_t)base*DI + d];
    float xv  = g_xc[(size_t)base*DI + d];
    float Ev  = g_e [(size_t)base*DI + d];
    for (int t = 0; t < CT; t++) {
        float dtn = 0.f, xn = 0.f, En = 0.f;
        if (t + 1 < CT) {
            size_t nr = (size_t)(base+t+1)*DI + d;
            dtn = g_dt[nr]; xn = g_xc[nr]; En = g_e[nr];
        }
        float c = dtv * xv;
        float dA[DS];
        if (fast) {
            powers16(dA, Ev);
        } else {
            #pragma unroll
            for (int s = 0; s < DS; s++) dA[s] = __expf(A[s]*dtv);
        }
        float acc = 0.f;
        #pragma unroll
        for (int s = 0; s < DS; s++) {
            h[s] = dA[s]*h[s] + c*sBC[t][s];
            acc += h[s]*sBC[t][16+s];
        }
        size_t row = base + t;
        float zv = g_xz[row*(2*DI) + DI + d];     // already silu'd by in_proj
        g_y[row*DI + d] = (acc + Dd*xv) * zv;
        dtv = dtn; xv = xn; Ev = En;
    }
}

// ---------------------------------------------------------------------------
// Host side
// ---------------------------------------------------------------------------
extern "C" void kernel_launch(void* const* d_in, const int* in_sizes, int n_in,
                              void* d_out, int out_size) {
    const int*   ids  = (const int*)  d_in[0];
    const float* emb  = (const float*)d_in[1];
    const float* inw  = (const float*)d_in[2];   // (NL, 2*DI, DM)
    const float* cw   = (const float*)d_in[3];   // (NL, DI, 4)
    const float* cb   = (const float*)d_in[4];   // (NL, DI)
    const float* xw   = (const float*)d_in[5];   // (NL, 48, DI)
    const float* dtw  = (const float*)d_in[6];   // (NL, DI, DR)
    const float* dtb  = (const float*)d_in[7];   // (NL, DI)
    const float* alog = (const float*)d_in[8];   // (NL, DI, DS)
    const float* Dp   = (const float*)d_in[9];   // (NL, DI)
    const float* ow   = (const float*)d_in[10];  // (NL, DM, DI)
    const float* nw   = (const float*)d_in[11];  // (NL, DM)
    const float* nfw  = (const float*)d_in[12];  // (DM)
    const float* lmw  = (const float*)d_in[13];  // (20, DM)
    float* out = (float*)d_out;

    float *p_hn, *p_xz, *p_xc, *p_y, *p_h, *p_wall;
    cudaGetSymbolAddress((void**)&p_hn,   g_hn);
    cudaGetSymbolAddress((void**)&p_xz,   g_xz);
    cudaGetSymbolAddress((void**)&p_xc,   g_xc);
    cudaGetSymbolAddress((void**)&p_y,    g_y);
    cudaGetSymbolAddress((void**)&p_h,    g_h);
    cudaGetSymbolAddress((void**)&p_wall, g_wall);

    embed_k<<<ROWS, DM>>>(ids, emb);
    wdt_k<<<NL*NDT*DI/256, 256>>>(xw, dtw);

    for (int l = 0; l < NL; l++) {
        norm_k<<<ROWS, DM>>>(nw + (size_t)l*DM, l == 0);

        // in_proj: (4096,256) x (1024,256)^T -> xz, silu on z half
        tgemm_k<1,128><<<dim3(8, 32), 256>>>(p_hn, DM, inw + (size_t)l*2*DI*DM,
                                             p_xz, 2*DI, 2*DI, DM, nullptr);
        // depthwise conv + silu
        conv_k<<<ROWS/4, 256>>>(cw + (size_t)l*DI*4, cb + (size_t)l*DI);

        // fused dt|B|C: (4096,512) x (544,512)^T -> g_dt, g_e, g_dbc
        tgemm_k<2,64><<<dim3(5, 64), 128>>>(p_xc, DI, p_wall + (size_t)l*NDT*DI,
                                            nullptr, 0, NDT, DI, dtb + (size_t)l*DI);
        // chunked selective scan
        scan1_k<<<BB*NC*2, 256>>>(alog + (size_t)l*DI*DS);
        combine_k<<<BB*DI*DS/256, 256>>>();
        scan2_k<<<BB*NC*2, 256>>>(alog + (size_t)l*DI*DS, Dp + (size_t)l*DI);

        // out_proj: (4096,512) x (256,512)^T -> h
        tgemm_k<0,64><<<dim3(2, 64), 128>>>(p_y, DI, ow + (size_t)l*DM*DI,
                                            p_h, DM, DM, DI, nullptr);
    }

    // final residual + norm + lm_head
    norm_k<<<ROWS, DM>>>(nfw, 0);
    gemm_k<<<dim3(1, 32), 256>>>(p_hn, DM, lmw, out, 20, 20, DM);
}